// round 5
// baseline (speedup 1.0000x reference)
#include <cuda_runtime.h>

static constexpr int B_  = 16;
static constexpr int H_  = 2048;
static constexpr int I_  = 1024;
static constexpr int NT  = 256;   // 8 warps; each thread owns 8 columns (2 float4 groups)

__device__ __forceinline__ float flg2(float x){ float r; asm("lg2.approx.f32 %0,%1;" : "=f"(r) : "f"(x)); return r; }
__device__ __forceinline__ float frcp(float x){ float r; asm("rcp.approx.f32 %0,%1;" : "=f"(r) : "f"(x)); return r; }
__device__ __forceinline__ float fex2(float x){ float r; asm("ex2.approx.f32 %0,%1;" : "=f"(r) : "f"(x)); return r; }

// 1 / max(-ln(u)+1e-10, 1-u).  1-u is the exact 1st-order value of -ln(u)
// near u=1 and always <= -ln(u); the max picks whichever branch is accurate
// (lg2.approx's 2^-22 abs error only matters near u=1). u=0 -> lg2=-inf ->
// t=+inf -> w=0 (reference weight there is negligibly small; cancels in num/den).
__device__ __forceinline__ float gw(float u) {
    float t = fmaf(flg2(u), -0.6931471805599453f, 1e-10f);
    t = fmaxf(t, 1.0f - u);
    return frcp(t);
}

__global__ __launch_bounds__(NT, 6) void reservoir_cell_kernel(
    const float* __restrict__ x_t,         // (B, I)
    const float* __restrict__ h_prev,      // (B, H)
    const float* __restrict__ W_ih_w,      // (H, I)
    const float* __restrict__ W_ih_b,      // (H,)
    const float* __restrict__ W_hh,        // (H, H)
    const float* __restrict__ hh_mask,     // (H, H)
    const float* __restrict__ temperature, // (1,)
    const float* __restrict__ gumbel,      // (B, H, H) uniform(0,1)
    float* __restrict__ out)               // (B, H)
{
    __shared__ float  s_red[8];
    __shared__ float  s_ic[B_];
    __shared__ float2 s_part[B_][NT];      // 32 KB: per-thread (num,den) partials

    const int o   = blockIdx.x;
    const int tid = threadIdx.x;
    const int wid = tid >> 5;
    const int lid = tid & 31;

    // logits scale folded with log2(e): phase 1 works directly in log2 domain
    const float s_l2 = 1.4426950408889634f / fmaxf(temperature[0], 1e-3f);

    // ---------- phase 1: row logits (log2 domain), block max, se[8] in regs ----------
    const float4* wrow = reinterpret_cast<const float4*>(W_hh    + (size_t)o * H_);
    const float4* mrow = reinterpret_cast<const float4*>(hh_mask + (size_t)o * H_);
    float4 wa = wrow[tid], wb = wrow[tid + NT];
    float4 ma = mrow[tid], mb = mrow[tid + NT];
    float e[8];
    e[0] = wa.x*ma.x*s_l2; e[1] = wa.y*ma.y*s_l2; e[2] = wa.z*ma.z*s_l2; e[3] = wa.w*ma.w*s_l2;
    e[4] = wb.x*mb.x*s_l2; e[5] = wb.y*mb.y*s_l2; e[6] = wb.z*mb.z*s_l2; e[7] = wb.w*mb.w*s_l2;

    float m = e[0];
    #pragma unroll
    for (int j = 1; j < 8; j++) m = fmaxf(m, e[j]);
    #pragma unroll
    for (int s = 16; s; s >>= 1) m = fmaxf(m, __shfl_xor_sync(0xffffffffu, m, s));
    if (lid == 0) s_red[wid] = m;
    __syncthreads();
    m = s_red[0];
    #pragma unroll
    for (int j = 1; j < 8; j++) m = fmaxf(m, s_red[j]);

    float se[8];
    #pragma unroll
    for (int j = 0; j < 8; j++) se[j] = fex2(e[j] - m);

    // ---------- phase 2: input contribution; warp w -> batches w and w+8 ----------
    {
        const float4* wr = reinterpret_cast<const float4*>(W_ih_w + (size_t)o * I_);
        const float4* x0 = reinterpret_cast<const float4*>(x_t + (size_t)wid * I_);
        const float4* x1 = reinterpret_cast<const float4*>(x_t + (size_t)(wid + 8) * I_);
        float a0 = 0.f, a1 = 0.f;
        #pragma unroll
        for (int k = lid; k < I_ / 4; k += 32) {
            float4 wv = wr[k];
            float4 v0 = x0[k];
            float4 v1 = x1[k];
            a0 = fmaf(wv.x, v0.x, a0); a0 = fmaf(wv.y, v0.y, a0);
            a0 = fmaf(wv.z, v0.z, a0); a0 = fmaf(wv.w, v0.w, a0);
            a1 = fmaf(wv.x, v1.x, a1); a1 = fmaf(wv.y, v1.y, a1);
            a1 = fmaf(wv.z, v1.z, a1); a1 = fmaf(wv.w, v1.w, a1);
        }
        #pragma unroll
        for (int s = 16; s; s >>= 1) {
            a0 += __shfl_xor_sync(0xffffffffu, a0, s);
            a1 += __shfl_xor_sync(0xffffffffu, a1, s);
        }
        if (lid == 0) {
            float bias = W_ih_b[o];
            s_ic[wid]     = a0 + bias;
            s_ic[wid + 8] = a1 + bias;
        }
    }

    // ---------- phase 3: stream gumbel (evict-first); pointer-increment addressing ----------
    const size_t bstride4 = (size_t)H_ * H_ / 4;           // float4 stride between batches
    const float4* gu = reinterpret_cast<const float4*>(gumbel + (size_t)o * H_) + tid;
    const float4* pf = gu + bstride4;                      // prefetch: batch b+1
    const float4* hp = reinterpret_cast<const float4*>(h_prev) + tid;
    float2* sp = &s_part[0][tid];

    float4 ua = __ldcs(gu);
    float4 ub = __ldcs(gu + NT);

    #pragma unroll 1
    for (int b = 0; b < B_; b++) {
        const float4 na  = __ldcs(pf);                     // re-reads batch 15 on last iter
        const float4 nbv = __ldcs(pf + NT);
        const float4 ha  = __ldg(hp);
        const float4 hb  = __ldg(hp + NT);

        float num = 0.f, den = 0.f;
        {
            float w;
            w = se[0] * gw(ua.x); num = fmaf(w, ha.x, num); den += w;
            w = se[1] * gw(ua.y); num = fmaf(w, ha.y, num); den += w;
            w = se[2] * gw(ua.z); num = fmaf(w, ha.z, num); den += w;
            w = se[3] * gw(ua.w); num = fmaf(w, ha.w, num); den += w;
            w = se[4] * gw(ub.x); num = fmaf(w, hb.x, num); den += w;
            w = se[5] * gw(ub.y); num = fmaf(w, hb.y, num); den += w;
            w = se[6] * gw(ub.z); num = fmaf(w, hb.z, num); den += w;
            w = se[7] * gw(ub.w); num = fmaf(w, hb.w, num); den += w;
        }
        *sp = make_float2(num, den);                       // contiguous 256B/warp, no conflicts

        ua = na; ub = nbv;
        pf += (b < B_ - 2) ? bstride4 : 0;                 // clamp: stay in-bounds
        hp += H_ / 4;
        sp += NT;
    }
    __syncthreads();

    // ---------- phase 4: one-time reduction; warp w -> batches 2w, 2w+1 ----------
    #pragma unroll
    for (int k = 0; k < 2; k++) {
        const int b = 2 * wid + k;
        const float4* row = reinterpret_cast<const float4*>(&s_part[b][0]);   // 128 float4
        float4 p0 = row[lid], p1 = row[lid + 32], p2 = row[lid + 64], p3 = row[lid + 96];
        float ns = (p0.x + p1.x) + (p2.x + p3.x) + (p0.z + p1.z) + (p2.z + p3.z);
        float ds = (p0.y + p1.y) + (p2.y + p3.y) + (p0.w + p1.w) + (p2.w + p3.w);
        #pragma unroll
        for (int s = 16; s; s >>= 1) {
            ns += __shfl_xor_sync(0xffffffffu, ns, s);
            ds += __shfl_xor_sync(0xffffffffu, ds, s);
        }
        if (lid == 0) out[(size_t)b * H_ + o] = tanhf(s_ic[b] + ns / ds);
    }
}

extern "C" void kernel_launch(void* const* d_in, const int* in_sizes, int n_in,
                              void* d_out, int out_size) {
    const float* x_t         = (const float*)d_in[0];
    const float* h_prev      = (const float*)d_in[1];
    const float* W_ih_w      = (const float*)d_in[2];
    const float* W_ih_b      = (const float*)d_in[3];
    const float* W_hh        = (const float*)d_in[4];
    const float* hh_mask     = (const float*)d_in[5];
    const float* temperature = (const float*)d_in[6];
    const float* gumbel      = (const float*)d_in[7];
    float* out = (float*)d_out;

    reservoir_cell_kernel<<<H_, NT>>>(x_t, h_prev, W_ih_w, W_ih_b, W_hh, hh_mask,
                                      temperature, gumbel, out);
}

// round 6
// speedup vs baseline: 1.2527x; 1.2527x over previous
#include <cuda_runtime.h>

static constexpr int B_  = 16;
static constexpr int H_  = 2048;
static constexpr int I_  = 1024;
static constexpr int NT  = 256;   // 8 warps; each thread owns 8 columns (2 float4 groups)

__device__ __forceinline__ float flg2(float x){ float r; asm("lg2.approx.f32 %0,%1;" : "=f"(r) : "f"(x)); return r; }
__device__ __forceinline__ float frcp(float x){ float r; asm("rcp.approx.f32 %0,%1;" : "=f"(r) : "f"(x)); return r; }
__device__ __forceinline__ float fex2(float x){ float r; asm("ex2.approx.f32 %0,%1;" : "=f"(r) : "f"(x)); return r; }

// 1 / max(-ln(u)+1e-10, 1-u).  1-u is the exact 1st-order value of -ln(u)
// near u=1 and always <= -ln(u); the max picks whichever branch is accurate
// (lg2.approx's 2^-22 abs error only matters near u=1). u=0 -> lg2=-inf ->
// t=+inf -> w=0 (reference weight there is negligibly small; cancels in num/den).
__device__ __forceinline__ float gw(float u) {
    float t = fmaf(flg2(u), -0.6931471805599453f, 1e-10f);
    t = fmaxf(t, 1.0f - u);
    return frcp(t);
}

__global__ __launch_bounds__(NT, 5) void reservoir_cell_kernel(
    const float* __restrict__ x_t,         // (B, I)
    const float* __restrict__ h_prev,      // (B, H)
    const float* __restrict__ W_ih_w,      // (H, I)
    const float* __restrict__ W_ih_b,      // (H,)
    const float* __restrict__ W_hh,        // (H, H)
    const float* __restrict__ hh_mask,     // (H, H)
    const float* __restrict__ temperature, // (1,)
    const float* __restrict__ gumbel,      // (B, H, H) uniform(0,1)
    float* __restrict__ out)               // (B, H)
{
    __shared__ float  s_red[8];
    __shared__ float  s_ic[B_];
    __shared__ float2 s_part[B_][NT];      // 32 KB: per-thread (num,den) partials

    const int o   = blockIdx.x;
    const int tid = threadIdx.x;
    const int wid = tid >> 5;
    const int lid = tid & 31;

    // logits scale folded with log2(e): phase 1 works directly in log2 domain
    const float s_l2 = 1.4426950408889634f / fmaxf(temperature[0], 1e-3f);

    // ---------- phase 1: row logits (log2 domain), block max, se[8] in regs ----------
    const float4* wrow = reinterpret_cast<const float4*>(W_hh    + (size_t)o * H_);
    const float4* mrow = reinterpret_cast<const float4*>(hh_mask + (size_t)o * H_);
    float4 wa = wrow[tid], wb = wrow[tid + NT];
    float4 ma = mrow[tid], mb = mrow[tid + NT];
    float e[8];
    e[0] = wa.x*ma.x*s_l2; e[1] = wa.y*ma.y*s_l2; e[2] = wa.z*ma.z*s_l2; e[3] = wa.w*ma.w*s_l2;
    e[4] = wb.x*mb.x*s_l2; e[5] = wb.y*mb.y*s_l2; e[6] = wb.z*mb.z*s_l2; e[7] = wb.w*mb.w*s_l2;

    float m = e[0];
    #pragma unroll
    for (int j = 1; j < 8; j++) m = fmaxf(m, e[j]);
    #pragma unroll
    for (int s = 16; s; s >>= 1) m = fmaxf(m, __shfl_xor_sync(0xffffffffu, m, s));
    if (lid == 0) s_red[wid] = m;
    __syncthreads();
    m = s_red[0];
    #pragma unroll
    for (int j = 1; j < 8; j++) m = fmaxf(m, s_red[j]);

    float se[8];
    #pragma unroll
    for (int j = 0; j < 8; j++) se[j] = fex2(e[j] - m);

    // ---------- phase 2 (moved after stream loop): see below ----------

    // ---------- phase 3: stream gumbel (evict-first); pointer-increment addressing ----------
    const size_t bstride4 = (size_t)H_ * H_ / 4;           // float4 stride between batches
    const float4* gu = reinterpret_cast<const float4*>(gumbel + (size_t)o * H_) + tid;
    const float4* pf = gu + bstride4;                      // prefetch: batch b+1
    const float4* hp = reinterpret_cast<const float4*>(h_prev) + tid;
    float2* sp = &s_part[0][tid];

    float4 ua = __ldcs(gu);
    float4 ub = __ldcs(gu + NT);

    #pragma unroll 4
    for (int b = 0; b < B_; b++) {
        const float4 na  = __ldcs(pf);                     // re-reads batch 15 on last iter
        const float4 nbv = __ldcs(pf + NT);
        const float4 ha  = __ldg(hp);
        const float4 hb  = __ldg(hp + NT);

        float num = 0.f, den = 0.f;
        {
            float w;
            w = se[0] * gw(ua.x); num = fmaf(w, ha.x, num); den += w;
            w = se[1] * gw(ua.y); num = fmaf(w, ha.y, num); den += w;
            w = se[2] * gw(ua.z); num = fmaf(w, ha.z, num); den += w;
            w = se[3] * gw(ua.w); num = fmaf(w, ha.w, num); den += w;
            w = se[4] * gw(ub.x); num = fmaf(w, hb.x, num); den += w;
            w = se[5] * gw(ub.y); num = fmaf(w, hb.y, num); den += w;
            w = se[6] * gw(ub.z); num = fmaf(w, hb.z, num); den += w;
            w = se[7] * gw(ub.w); num = fmaf(w, hb.w, num); den += w;
        }
        *sp = make_float2(num, den);                       // contiguous 256B/warp, no conflicts

        ua = na; ub = nbv;
        pf += (b < B_ - 2) ? bstride4 : 0;                 // clamp: stay in-bounds
        hp += H_ / 4;
        sp += NT;
    }

    // ---------- phase 2: input contribution; warp w -> batches w and w+8 ----------
    // (after the gumbel stream so the DRAM-critical loop starts ASAP; this
    //  L2-resident dot overlaps with other CTAs' streaming)
    {
        const float4* wr = reinterpret_cast<const float4*>(W_ih_w + (size_t)o * I_);
        const float4* x0 = reinterpret_cast<const float4*>(x_t + (size_t)wid * I_);
        const float4* x1 = reinterpret_cast<const float4*>(x_t + (size_t)(wid + 8) * I_);
        float a0 = 0.f, a1 = 0.f;
        #pragma unroll
        for (int k = lid; k < I_ / 4; k += 32) {
            float4 wv = wr[k];
            float4 v0 = x0[k];
            float4 v1 = x1[k];
            a0 = fmaf(wv.x, v0.x, a0); a0 = fmaf(wv.y, v0.y, a0);
            a0 = fmaf(wv.z, v0.z, a0); a0 = fmaf(wv.w, v0.w, a0);
            a1 = fmaf(wv.x, v1.x, a1); a1 = fmaf(wv.y, v1.y, a1);
            a1 = fmaf(wv.z, v1.z, a1); a1 = fmaf(wv.w, v1.w, a1);
        }
        #pragma unroll
        for (int s = 16; s; s >>= 1) {
            a0 += __shfl_xor_sync(0xffffffffu, a0, s);
            a1 += __shfl_xor_sync(0xffffffffu, a1, s);
        }
        if (lid == 0) {
            float bias = W_ih_b[o];
            s_ic[wid]     = a0 + bias;
            s_ic[wid + 8] = a1 + bias;
        }
    }
    __syncthreads();

    // ---------- phase 4: one-time reduction; warp w -> batches 2w, 2w+1 ----------
    #pragma unroll
    for (int k = 0; k < 2; k++) {
        const int b = 2 * wid + k;
        const float4* row = reinterpret_cast<const float4*>(&s_part[b][0]);   // 128 float4
        float4 p0 = row[lid], p1 = row[lid + 32], p2 = row[lid + 64], p3 = row[lid + 96];
        float ns = (p0.x + p1.x) + (p2.x + p3.x) + (p0.z + p1.z) + (p2.z + p3.z);
        float ds = (p0.y + p1.y) + (p2.y + p3.y) + (p0.w + p1.w) + (p2.w + p3.w);
        #pragma unroll
        for (int s = 16; s; s >>= 1) {
            ns += __shfl_xor_sync(0xffffffffu, ns, s);
            ds += __shfl_xor_sync(0xffffffffu, ds, s);
        }
        if (lid == 0) out[(size_t)b * H_ + o] = tanhf(s_ic[b] + ns / ds);
    }
}

extern "C" void kernel_launch(void* const* d_in, const int* in_sizes, int n_in,
                              void* d_out, int out_size) {
    const float* x_t         = (const float*)d_in[0];
    const float* h_prev      = (const float*)d_in[1];
    const float* W_ih_w      = (const float*)d_in[2];
    const float* W_ih_b      = (const float*)d_in[3];
    const float* W_hh        = (const float*)d_in[4];
    const float* hh_mask     = (const float*)d_in[5];
    const float* temperature = (const float*)d_in[6];
    const float* gumbel      = (const float*)d_in[7];
    float* out = (float*)d_out;

    reservoir_cell_kernel<<<H_, NT>>>(x_t, h_prev, W_ih_w, W_ih_b, W_hh, hh_mask,
                                      temperature, gumbel, out);
}

// round 7
// speedup vs baseline: 1.3462x; 1.0747x over previous
#include <cuda_runtime.h>

static constexpr int B_  = 16;
static constexpr int H_  = 2048;
static constexpr int I_  = 1024;
static constexpr int NT  = 256;   // 8 warps; each thread owns 8 columns (2 float4 groups)

__device__ __forceinline__ float flg2(float x){ float r; asm("lg2.approx.f32 %0,%1;" : "=f"(r) : "f"(x)); return r; }
__device__ __forceinline__ float frcp(float x){ float r; asm("rcp.approx.f32 %0,%1;" : "=f"(r) : "f"(x)); return r; }
__device__ __forceinline__ float fex2(float x){ float r; asm("ex2.approx.f32 %0,%1;" : "=f"(r) : "f"(x)); return r; }

// w = se / (-ln u) = (-se*log2e) * rcp(lg2(u)).
// Clamp lg2(u) <= -4e-8 (|lg2| of the largest float < 1): protects against
// lg2.approx's 2^-22 abs error flipping the sign near u=1; the clamped weight
// is huge -> dominates num AND den -> output -> h of that element, which is
// the true u->1 limit, so the approximation error cancels.
// u = 0 -> lg2 = -inf -> rcp = -0 -> w = +0 (reference weight there ~0.04*se,
// negligible among a ~2e4*se row sum).
__device__ __forceinline__ float gwr(float u) {
    return frcp(fminf(flg2(u), -4e-8f));   // negative result; nse sign restores +
}

__global__ __launch_bounds__(NT, 5) void reservoir_cell_kernel(
    const float* __restrict__ x_t,         // (B, I)
    const float* __restrict__ h_prev,      // (B, H)
    const float* __restrict__ W_ih_w,      // (H, I)
    const float* __restrict__ W_ih_b,      // (H,)
    const float* __restrict__ W_hh,        // (H, H)
    const float* __restrict__ hh_mask,     // (H, H)
    const float* __restrict__ temperature, // (1,)
    const float* __restrict__ gumbel,      // (B, H, H) uniform(0,1)
    float* __restrict__ out)               // (B, H)
{
    __shared__ float  s_red[8];
    __shared__ float  s_ic[B_];
    __shared__ float2 s_part[B_][NT];      // 32 KB: per-thread (num,den) partials

    const int o   = blockIdx.x;
    const int tid = threadIdx.x;
    const int wid = tid >> 5;
    const int lid = tid & 31;

    // logits scale folded with log2(e): phase 1 works directly in log2 domain
    const float s_l2 = 1.4426950408889634f / fmaxf(temperature[0], 1e-3f);

    // ---------- phase 1: row logits (log2 domain), block max, nse[8] in regs ----------
    const float4* wrow = reinterpret_cast<const float4*>(W_hh    + (size_t)o * H_);
    const float4* mrow = reinterpret_cast<const float4*>(hh_mask + (size_t)o * H_);
    float4 wa = wrow[tid], wb = wrow[tid + NT];
    float4 ma = mrow[tid], mb = mrow[tid + NT];
    float e[8];
    e[0] = wa.x*ma.x*s_l2; e[1] = wa.y*ma.y*s_l2; e[2] = wa.z*ma.z*s_l2; e[3] = wa.w*ma.w*s_l2;
    e[4] = wb.x*mb.x*s_l2; e[5] = wb.y*mb.y*s_l2; e[6] = wb.z*mb.z*s_l2; e[7] = wb.w*mb.w*s_l2;

    float m = e[0];
    #pragma unroll
    for (int j = 1; j < 8; j++) m = fmaxf(m, e[j]);
    #pragma unroll
    for (int s = 16; s; s >>= 1) m = fmaxf(m, __shfl_xor_sync(0xffffffffu, m, s));
    if (lid == 0) s_red[wid] = m;
    __syncthreads();
    m = s_red[0];
    #pragma unroll
    for (int j = 1; j < 8; j++) m = fmaxf(m, s_red[j]);

    // nse = -se * log2(e): sign + 1/ln2 folded so hot loop does w = nse * rcp(lg2 u)
    float nse[8];
    #pragma unroll
    for (int j = 0; j < 8; j++) nse[j] = -1.4426950408889634f * fex2(e[j] - m);

    // ---------- phase 3: stream gumbel (evict-first); pointer-increment addressing ----------
    const size_t bstride4 = (size_t)H_ * H_ / 4;           // float4 stride between batches
    const float4* gu = reinterpret_cast<const float4*>(gumbel + (size_t)o * H_) + tid;
    const float4* pf = gu + bstride4;                      // prefetch: batch b+1
    const float4* hp = reinterpret_cast<const float4*>(h_prev) + tid;
    float2* sp = &s_part[0][tid];

    float4 ua = __ldcs(gu);
    float4 ub = __ldcs(gu + NT);

    #pragma unroll 4
    for (int b = 0; b < B_; b++) {
        const float4 na  = __ldcs(pf);                     // re-reads batch 15 on last iter
        const float4 nbv = __ldcs(pf + NT);
        const float4 ha  = __ldg(hp);
        const float4 hb  = __ldg(hp + NT);

        float num = 0.f, den = 0.f;
        {
            float w;
            w = nse[0] * gwr(ua.x); num = fmaf(w, ha.x, num); den += w;
            w = nse[1] * gwr(ua.y); num = fmaf(w, ha.y, num); den += w;
            w = nse[2] * gwr(ua.z); num = fmaf(w, ha.z, num); den += w;
            w = nse[3] * gwr(ua.w); num = fmaf(w, ha.w, num); den += w;
            w = nse[4] * gwr(ub.x); num = fmaf(w, hb.x, num); den += w;
            w = nse[5] * gwr(ub.y); num = fmaf(w, hb.y, num); den += w;
            w = nse[6] * gwr(ub.z); num = fmaf(w, hb.z, num); den += w;
            w = nse[7] * gwr(ub.w); num = fmaf(w, hb.w, num); den += w;
        }
        *sp = make_float2(num, den);                       // contiguous 256B/warp, no conflicts

        ua = na; ub = nbv;
        pf += (b < B_ - 2) ? bstride4 : 0;                 // clamp: stay in-bounds
        hp += H_ / 4;
        sp += NT;
    }

    // ---------- phase 2: input contribution; warp w -> batches w and w+8 ----------
    // (after the gumbel stream so the DRAM-critical loop starts ASAP)
    {
        const float4* wr = reinterpret_cast<const float4*>(W_ih_w + (size_t)o * I_);
        const float4* x0 = reinterpret_cast<const float4*>(x_t + (size_t)wid * I_);
        const float4* x1 = reinterpret_cast<const float4*>(x_t + (size_t)(wid + 8) * I_);
        float a0 = 0.f, a1 = 0.f;
        #pragma unroll
        for (int k = lid; k < I_ / 4; k += 32) {
            float4 wv = wr[k];
            float4 v0 = x0[k];
            float4 v1 = x1[k];
            a0 = fmaf(wv.x, v0.x, a0); a0 = fmaf(wv.y, v0.y, a0);
            a0 = fmaf(wv.z, v0.z, a0); a0 = fmaf(wv.w, v0.w, a0);
            a1 = fmaf(wv.x, v1.x, a1); a1 = fmaf(wv.y, v1.y, a1);
            a1 = fmaf(wv.z, v1.z, a1); a1 = fmaf(wv.w, v1.w, a1);
        }
        #pragma unroll
        for (int s = 16; s; s >>= 1) {
            a0 += __shfl_xor_sync(0xffffffffu, a0, s);
            a1 += __shfl_xor_sync(0xffffffffu, a1, s);
        }
        if (lid == 0) {
            float bias = W_ih_b[o];
            s_ic[wid]     = a0 + bias;
            s_ic[wid + 8] = a1 + bias;
        }
    }
    __syncthreads();

    // ---------- phase 4: one-time reduction; warp w -> batches 2w, 2w+1 ----------
    #pragma unroll
    for (int k = 0; k < 2; k++) {
        const int b = 2 * wid + k;
        const float4* row = reinterpret_cast<const float4*>(&s_part[b][0]);   // 128 float4
        float4 p0 = row[lid], p1 = row[lid + 32], p2 = row[lid + 64], p3 = row[lid + 96];
        float ns = (p0.x + p1.x) + (p2.x + p3.x) + (p0.z + p1.z) + (p2.z + p3.z);
        float ds = (p0.y + p1.y) + (p2.y + p3.y) + (p0.w + p1.w) + (p2.w + p3.w);
        #pragma unroll
        for (int s = 16; s; s >>= 1) {
            ns += __shfl_xor_sync(0xffffffffu, ns, s);
            ds += __shfl_xor_sync(0xffffffffu, ds, s);
        }
        if (lid == 0) out[(size_t)b * H_ + o] = tanhf(s_ic[b] + ns / ds);
    }
}

extern "C" void kernel_launch(void* const* d_in, const int* in_sizes, int n_in,
                              void* d_out, int out_size) {
    const float* x_t         = (const float*)d_in[0];
    const float* h_prev      = (const float*)d_in[1];
    const float* W_ih_w      = (const float*)d_in[2];
    const float* W_ih_b      = (const float*)d_in[3];
    const float* W_hh        = (const float*)d_in[4];
    const float* hh_mask     = (const float*)d_in[5];
    const float* temperature = (const float*)d_in[6];
    const float* gumbel      = (const float*)d_in[7];
    float* out = (float*)d_out;

    reservoir_cell_kernel<<<H_, NT>>>(x_t, h_prev, W_ih_w, W_ih_b, W_hh, hh_mask,
                                      temperature, gumbel, out);
}